// round 13
// baseline (speedup 1.0000x reference)
#include <cuda_runtime.h>

#define NN 100000
#define EE 3200000

// ---------------------------------------------------------------------------
// Scratch layout (float units). 28,800,112 floats ~ 115 MB.
// ---------------------------------------------------------------------------
__device__ float g_scratch[28800112];

static const long O_CNT  = 0;         // int[400000] degree counts
static const long O_OFF  = 400000;    // int[400000] CSR start offsets (global)
static const long O_CUR  = 800000;    // int[400000] build cursors
static const long O_BSUM = 1200000;   // int[98] scan block sums (pad to 112)
static const long O_DINV = 1200112;   // float[400000]
static const long O_U1   = 1600112;   // float[N*16]
static const long O_U2   = 3200112;
static const long O_U3   = 4800112;
static const long O_U4   = 6400112;
static const long O_U5   = 8000112;   // stride 16 (cols 10..15 zero)
static const long O_HP   = 9600112;
static const long O_HC1  = 11200112;
static const long O_HC2  = 12800112;
static const long O_HF   = 14400112;
static const long O_CSR  = 16000112;  // int[12800000] src ids, CSR order

// ---------------------------------------------------------------------------
// Degree histogram over dst for all 4 graphs (one launch).
// ---------------------------------------------------------------------------
__global__ void count4_k(const int* __restrict__ d0, const int* __restrict__ d1,
                         const int* __restrict__ d2, const int* __restrict__ d3,
                         int* __restrict__ cnt) {
    long t = (long)blockIdx.x * 256 + threadIdx.x;
    if (t >= 4L * EE) return;
    int g = (int)(t / EE);
    int e = (int)(t - (long)g * EE);
    const int* d = (g == 0) ? d0 : (g == 1) ? d1 : (g == 2) ? d2 : d3;
    atomicAdd(&cnt[g * NN + __ldg(d + e)], 1);
}

// ---------------------------------------------------------------------------
// Exclusive scan of cnt[400000] -> off, cur  (3 kernels; 4096 items/block)
// ---------------------------------------------------------------------------
__global__ __launch_bounds__(512) void scanA_k(const int* __restrict__ cnt,
                                               int* __restrict__ bsum) {
    int t = threadIdx.x, b = blockIdx.x;
    long base = (long)b * 4096 + t * 8;
    int s = 0;
#pragma unroll
    for (int j = 0; j < 8; j++) {
        long i = base + j;
        if (i < 400000) s += __ldg(cnt + i);
    }
#pragma unroll
    for (int o = 16; o; o >>= 1) s += __shfl_down_sync(0xFFFFFFFFu, s, o);
    __shared__ int wsum[16];
    if ((t & 31) == 0) wsum[t >> 5] = s;
    __syncthreads();
    if (t < 16) {
        int v = wsum[t];
#pragma unroll
        for (int o = 8; o; o >>= 1) v += __shfl_down_sync(0xFFFFu, v, o, 16);
        if (t == 0) bsum[b] = v;
    }
}

__global__ void scanB_k(int* __restrict__ bsum) {   // 128 threads, 98 values
    int t = threadIdx.x;
    int v = (t < 98) ? bsum[t] : 0;
    int lane = t & 31, w = t >> 5;
    int x = v;
#pragma unroll
    for (int o = 1; o < 32; o <<= 1) {
        int y = __shfl_up_sync(0xFFFFFFFFu, x, o);
        if (lane >= o) x += y;
    }
    __shared__ int ws[4];
    if (lane == 31) ws[w] = x;
    __syncthreads();
    int add = 0;
    for (int k = 0; k < w; k++) add += ws[k];
    if (t < 98) bsum[t] = (x - v) + add;   // exclusive
}

__global__ __launch_bounds__(512) void scanC_k(const int* __restrict__ cnt,
                                               const int* __restrict__ bsum,
                                               int* __restrict__ off,
                                               int* __restrict__ cur,
                                               float* __restrict__ dinv) {
    int t = threadIdx.x, b = blockIdx.x;
    long base = (long)b * 4096 + t * 8;
    int loc[8];
    int s = 0;
#pragma unroll
    for (int j = 0; j < 8; j++) {
        long i = base + j;
        loc[j] = (i < 400000) ? __ldg(cnt + i) : 0;
        s += loc[j];
    }
    int lane = t & 31, w = t >> 5;
    int x = s;
#pragma unroll
    for (int o = 1; o < 32; o <<= 1) {
        int y = __shfl_up_sync(0xFFFFFFFFu, x, o);
        if (lane >= o) x += y;
    }
    __shared__ int wsum[16];
    __shared__ int woff[16];
    if (lane == 31) wsum[w] = x;
    __syncthreads();
    if (t < 16) {
        int v = wsum[t];
        int xx = v;
#pragma unroll
        for (int o = 1; o < 16; o <<= 1) {
            int y = __shfl_up_sync(0xFFFFu, xx, o, 16);
            if (t >= o) xx += y;
        }
        woff[t] = xx - v;
    }
    __syncthreads();
    int run = (x - s) + woff[w] + bsum[b];
#pragma unroll
    for (int j = 0; j < 8; j++) {
        long i = base + j;
        if (i < 400000) {
            off[i] = run;
            cur[i] = run;
            dinv[i] = rsqrtf((float)loc[j] + 1.0f);
        }
        run += loc[j];
    }
}

// ---------------------------------------------------------------------------
// CSR fill: csr[pos] = src, pos = cursor[dst]++   (all 4 graphs, one launch)
// ---------------------------------------------------------------------------
__global__ void build4_k(const int* __restrict__ e0, const int* __restrict__ e1,
                         const int* __restrict__ e2, const int* __restrict__ e3,
                         int* __restrict__ cur, int* __restrict__ csr) {
    long t = (long)blockIdx.x * 256 + threadIdx.x;
    if (t >= 4L * EE) return;
    int g = (int)(t / EE);
    int e = (int)(t - (long)g * EE);
    const int* E = (g == 0) ? e0 : (g == 1) ? e1 : (g == 2) ? e2 : e3;
    int s = __ldg(E + e);
    int d = __ldg(E + EE + e);
    int pos = atomicAdd(cur + g * NN + d, 1);
    csr[pos] = s;
}

// ---------------------------------------------------------------------------
// GEMM (quad-split): 256 threads, 64 nodes/block, 4 threads per node each
// computing 4 of the 16 outputs over the full K range.
// U[n][f] = dinv[n] * sum_k X[n][k] * W[k][f]
// ---------------------------------------------------------------------------
template<int F>
__global__ __launch_bounds__(256) void gemm_k(const float* __restrict__ X,
                                              const float* __restrict__ W,
                                              const float* __restrict__ dinv,
                                              float* __restrict__ U) {
    constexpr int FP = 132;
    __shared__ float xs[64 * FP];   // 33792 B
    __shared__ float ws[FP * 16];   //  8448 B
    const int tid = threadIdx.x;
    const int node0 = blockIdx.x * 64;

    for (int i = tid; i < FP * 16; i += 256)
        ws[i] = (i < F * 16) ? W[i] : 0.f;

    int valid = NN - node0; if (valid > 64) valid = 64;
    const int lim = valid * F;
    for (int i = tid; i < lim; i += 256) {
        int r = i / F;
        int k = i - r * F;
        xs[r * FP + k] = X[(long)node0 * F + i];
    }
    constexpr int PAD = FP - F;
    for (int i = tid; i < 64 * PAD; i += 256) {
        int r = i / PAD;
        int c = i - r * PAD;
        xs[r * FP + F + c] = 0.f;
    }
    __syncthreads();

    const int nl = tid >> 2;
    const int q  = tid & 3;
    const int n  = node0 + nl;
    if (n >= NN) return;

    float4 acc = make_float4(0.f, 0.f, 0.f, 0.f);
    const float* xr = xs + nl * FP;
    const float* wq = ws + q * 4;

#pragma unroll
    for (int k = 0; k < FP; k += 4) {
        float4 xv = *(const float4*)(xr + k);
        float4 w0 = *(const float4*)(wq + (k + 0) * 16);
        float4 w1 = *(const float4*)(wq + (k + 1) * 16);
        float4 w2 = *(const float4*)(wq + (k + 2) * 16);
        float4 w3 = *(const float4*)(wq + (k + 3) * 16);
        acc.x = fmaf(xv.x, w0.x, acc.x); acc.y = fmaf(xv.x, w0.y, acc.y);
        acc.z = fmaf(xv.x, w0.z, acc.z); acc.w = fmaf(xv.x, w0.w, acc.w);
        acc.x = fmaf(xv.y, w1.x, acc.x); acc.y = fmaf(xv.y, w1.y, acc.y);
        acc.z = fmaf(xv.y, w1.z, acc.z); acc.w = fmaf(xv.y, w1.w, acc.w);
        acc.x = fmaf(xv.z, w2.x, acc.x); acc.y = fmaf(xv.z, w2.y, acc.y);
        acc.z = fmaf(xv.z, w2.z, acc.z); acc.w = fmaf(xv.z, w2.w, acc.w);
        acc.x = fmaf(xv.w, w3.x, acc.x); acc.y = fmaf(xv.w, w3.y, acc.y);
        acc.z = fmaf(xv.w, w3.z, acc.z); acc.w = fmaf(xv.w, w3.w, acc.w);
    }

    const float dv = dinv[n];
    float4 r = make_float4(dv * acc.x, dv * acc.y, dv * acc.z, dv * acc.w);
    *(float4*)(U + (long)n * 16 + q * 4) = r;
}

// ---------------------------------------------------------------------------
// Gather + epilogue: one warp per node. Lanes split as 8 quads x 4 quarters.
// acc_q = sum over in-edges of u[src][4q..4q+3]; then
// h = dinv*(acc + u[n]) + b  [+ relu(rA)+rA]  [+ rB]
// ---------------------------------------------------------------------------
template<bool HAS_RA, bool HAS_RB>
__global__ __launch_bounds__(256) void gather_epi_k(
        const int* __restrict__ csr, const int* __restrict__ off,
        const int* __restrict__ cnt, const float* __restrict__ u,
        const float* __restrict__ dinv, const float* __restrict__ b,
        const float* __restrict__ rA, const float* __restrict__ rB,
        float* __restrict__ h, int gbase) {
    int n = (blockIdx.x * 256 + threadIdx.x) >> 5;
    if (n >= NN) return;
    int lane = threadIdx.x & 31;
    int quad = lane >> 2;
    int q    = lane & 3;
    int idx  = gbase + n;
    int start = __ldg(off + idx);
    int deg   = __ldg(cnt + idx);

    float4 acc = make_float4(0.f, 0.f, 0.f, 0.f);
    for (int base = 0; base < deg; base += 32) {
        int rem = deg - base;
        int nb = rem < 32 ? rem : 32;
        int sid = 0;
        if (lane < nb) sid = __ldg(csr + start + base + lane);
#pragma unroll
        for (int i = 0; i < 4; i++) {
            int ei = i * 8 + quad;
            int s = __shfl_sync(0xFFFFFFFFu, sid, ei);
            if (ei < nb) {
                float4 v = *(const float4*)(u + (long)s * 16 + q * 4);
                acc.x += v.x; acc.y += v.y; acc.z += v.z; acc.w += v.w;
            }
        }
    }
    // reduce across the 8 quads (lanes with equal q)
#pragma unroll
    for (int m = 4; m <= 16; m <<= 1) {
        acc.x += __shfl_xor_sync(0xFFFFFFFFu, acc.x, m);
        acc.y += __shfl_xor_sync(0xFFFFFFFFu, acc.y, m);
        acc.z += __shfl_xor_sync(0xFFFFFFFFu, acc.z, m);
        acc.w += __shfl_xor_sync(0xFFFFFFFFu, acc.w, m);
    }
    if (lane < 4) {   // lane == q here
        float dv = dinv[idx];
        float4 uu = *(const float4*)(u + (long)n * 16 + lane * 4);
        float4 bb = ((const float4*)b)[lane];
        float4 r;
        r.x = dv * (acc.x + uu.x) + bb.x;
        r.y = dv * (acc.y + uu.y) + bb.y;
        r.z = dv * (acc.z + uu.z) + bb.z;
        r.w = dv * (acc.w + uu.w) + bb.w;
        if (HAS_RA) {
            float4 t = ((const float4*)rA)[(long)n * 4 + lane];
            r.x += fmaxf(t.x, 0.f) + t.x;
            r.y += fmaxf(t.y, 0.f) + t.y;
            r.z += fmaxf(t.z, 0.f) + t.z;
            r.w += fmaxf(t.w, 0.f) + t.w;
        }
        if (HAS_RB) {
            float4 t = ((const float4*)rB)[(long)n * 4 + lane];
            r.x += t.x; r.y += t.y; r.z += t.z; r.w += t.w;
        }
        *(float4*)(h + (long)n * 16 + lane * 4) = r;
    }
}

// ---------------------------------------------------------------------------
// Layer-5 GEMM: u5[n] = dinv_fd[n] * (relu(hf[n]) @ We), stride 16, pad zeros
// ---------------------------------------------------------------------------
__global__ void gemm5_k(const float* __restrict__ hf, const float* __restrict__ We,
                        const float* __restrict__ dinv_fd, float* __restrict__ u5) {
    __shared__ float ws[160];
    if (threadIdx.x < 160) ws[threadIdx.x] = We[threadIdx.x];
    __syncthreads();
    int n = blockIdx.x * 256 + threadIdx.x;
    if (n >= NN) return;
    float xf[16];
    const float4* H = (const float4*)hf + (long)n * 4;
#pragma unroll
    for (int g = 0; g < 4; g++) {
        float4 v = H[g];
        xf[4 * g + 0] = fmaxf(v.x, 0.f);
        xf[4 * g + 1] = fmaxf(v.y, 0.f);
        xf[4 * g + 2] = fmaxf(v.z, 0.f);
        xf[4 * g + 3] = fmaxf(v.w, 0.f);
    }
    float acc[10];
#pragma unroll
    for (int f = 0; f < 10; f++) acc[f] = 0.f;
#pragma unroll
    for (int k = 0; k < 16; k++) {
        float xk = xf[k];
#pragma unroll
        for (int f = 0; f < 10; f++) acc[f] = fmaf(xk, ws[k * 10 + f], acc[f]);
    }
    float dv = dinv_fd[n];
    float o[16];
#pragma unroll
    for (int f = 0; f < 10; f++) o[f] = dv * acc[f];
#pragma unroll
    for (int f = 10; f < 16; f++) o[f] = 0.f;
    float4* U = (float4*)(u5 + (long)n * 16);
    U[0] = make_float4(o[0], o[1], o[2], o[3]);
    U[1] = make_float4(o[4], o[5], o[6], o[7]);
    U[2] = make_float4(o[8], o[9], o[10], o[11]);
    U[3] = make_float4(o[12], o[13], o[14], o[15]);
}

// ---------------------------------------------------------------------------
// Layer-5 gather + log_softmax (10 classes). Warp per node, same gather.
// ---------------------------------------------------------------------------
__global__ __launch_bounds__(256) void gather_final_k(
        const int* __restrict__ csr, const int* __restrict__ off,
        const int* __restrict__ cnt, const float* __restrict__ u,
        const float* __restrict__ dinv, const float* __restrict__ be,
        float* __restrict__ out, int gbase) {
    int n = (blockIdx.x * 256 + threadIdx.x) >> 5;
    if (n >= NN) return;
    int lane = threadIdx.x & 31;
    int quad = lane >> 2;
    int q    = lane & 3;
    int idx  = gbase + n;
    int start = __ldg(off + idx);
    int deg   = __ldg(cnt + idx);

    float4 acc = make_float4(0.f, 0.f, 0.f, 0.f);
    for (int base = 0; base < deg; base += 32) {
        int rem = deg - base;
        int nb = rem < 32 ? rem : 32;
        int sid = 0;
        if (lane < nb) sid = __ldg(csr + start + base + lane);
#pragma unroll
        for (int i = 0; i < 4; i++) {
            int ei = i * 8 + quad;
            int s = __shfl_sync(0xFFFFFFFFu, sid, ei);
            if (ei < nb) {
                float4 v = *(const float4*)(u + (long)s * 16 + q * 4);
                acc.x += v.x; acc.y += v.y; acc.z += v.z; acc.w += v.w;
            }
        }
    }
#pragma unroll
    for (int m = 4; m <= 16; m <<= 1) {
        acc.x += __shfl_xor_sync(0xFFFFFFFFu, acc.x, m);
        acc.y += __shfl_xor_sync(0xFFFFFFFFu, acc.y, m);
        acc.z += __shfl_xor_sync(0xFFFFFFFFu, acc.z, m);
        acc.w += __shfl_xor_sync(0xFFFFFFFFu, acc.w, m);
    }
    // lanes 0..3 hold quarter q = lane; classes 0..9 live in lanes 0,1,2
    float o0 = 0.f, o1 = 0.f, o2 = 0.f, o3 = 0.f;
    int nvalid = (lane == 0 || lane == 1) ? 4 : (lane == 2 ? 2 : 0);
    if (lane < 4) {
        float dv = dinv[idx];
        float4 uu = *(const float4*)(u + (long)n * 16 + lane * 4);
        o0 = dv * (acc.x + uu.x);
        o1 = dv * (acc.y + uu.y);
        o2 = dv * (acc.z + uu.z);
        o3 = dv * (acc.w + uu.w);
        int cb = lane * 4;
        if (nvalid > 0) o0 += __ldg(be + cb + 0);
        if (nvalid > 1) o1 += __ldg(be + cb + 1);
        if (nvalid > 2) o2 += __ldg(be + cb + 2);
        if (nvalid > 3) o3 += __ldg(be + cb + 3);
    }
    const float NEG = -3.0e38f;
    float m = NEG;
    if (nvalid > 0) m = fmaxf(m, o0);
    if (nvalid > 1) m = fmaxf(m, o1);
    if (nvalid > 2) m = fmaxf(m, o2);
    if (nvalid > 3) m = fmaxf(m, o3);
    m = fmaxf(m, __shfl_xor_sync(0xFFFFFFFFu, m, 1));
    m = fmaxf(m, __shfl_xor_sync(0xFFFFFFFFu, m, 2));
    float s = 0.f;
    if (nvalid > 0) s += expf(o0 - m);
    if (nvalid > 1) s += expf(o1 - m);
    if (nvalid > 2) s += expf(o2 - m);
    if (nvalid > 3) s += expf(o3 - m);
    s += __shfl_xor_sync(0xFFFFFFFFu, s, 1);
    s += __shfl_xor_sync(0xFFFFFFFFu, s, 2);
    float l = m + logf(s);
    long ob = (long)n * 10 + lane * 4;
    if (nvalid > 0) out[ob + 0] = o0 - l;
    if (nvalid > 1) out[ob + 1] = o1 - l;
    if (nvalid > 2) out[ob + 2] = o2 - l;
    if (nvalid > 3) out[ob + 3] = o3 - l;
}

// ---------------------------------------------------------------------------
// Launch
// ---------------------------------------------------------------------------
extern "C" void kernel_launch(void* const* d_in, const int* in_sizes, int n_in,
                              void* d_out, int out_size) {
    const float* xp  = (const float*)d_in[0];
    const float* xc1 = (const float*)d_in[1];
    const float* xc2 = (const float*)d_in[2];
    const float* xfd = (const float*)d_in[3];
    const int*   ep  = (const int*)d_in[4];
    const int*   ec1 = (const int*)d_in[5];
    const int*   ec2 = (const int*)d_in[6];
    const int*   efd = (const int*)d_in[7];
    const float* W1 = (const float*)d_in[8];
    const float* b1 = (const float*)d_in[9];
    const float* W2 = (const float*)d_in[10];
    const float* b2 = (const float*)d_in[11];
    const float* W3 = (const float*)d_in[12];
    const float* b3 = (const float*)d_in[13];
    const float* We = (const float*)d_in[14];
    const float* be = (const float*)d_in[15];
    float* out = (float*)d_out;

    float* S = nullptr;
    cudaGetSymbolAddress((void**)&S, g_scratch);

    int*   cnt  = (int*)(S + O_CNT);
    int*   off  = (int*)(S + O_OFF);
    int*   cur  = (int*)(S + O_CUR);
    int*   bsum = (int*)(S + O_BSUM);
    int*   csr  = (int*)(S + O_CSR);
    float* dinv = S + O_DINV;   // [parent | c1 | c2 | fd], each N
    float* u1 = S + O_U1, *u2 = S + O_U2, *u3 = S + O_U3, *u4 = S + O_U4, *u5 = S + O_U5;
    float* hp = S + O_HP, *hc1 = S + O_HC1, *hc2 = S + O_HC2, *hf = S + O_HF;

    const int GN = (NN + 255) / 256;                 // 391
    const int GG = (NN + 63) / 64;                   // 1563
    const int GC = (int)((4L * EE + 255) / 256);     // 50000
    const int GW = (NN * 32 + 255) / 256;            // 12500 (warp per node)

    // 1) degrees
    cudaMemsetAsync(cnt, 0, 400000 * sizeof(int));
    count4_k<<<GC, 256>>>(ep + EE, ec1 + EE, ec2 + EE, efd + EE, cnt);

    // 2) exclusive scan -> off, cur (+ dinv fused)
    scanA_k<<<98, 512>>>(cnt, bsum);
    scanB_k<<<1, 128>>>(bsum);
    scanC_k<<<98, 512>>>(cnt, bsum, off, cur, dinv);

    // 3) CSR fill
    build4_k<<<GC, 256>>>(ep, ec1, ec2, efd, cur, csr);

    // 4) dense GEMMs with dinv pre-scaling (u = dinv .* (x @ W))
    gemm_k<128><<<GG, 256>>>(xp,  W1, dinv + 0 * NN, u1);
    gemm_k<129><<<GG, 256>>>(xc1, W2, dinv + 1 * NN, u2);
    gemm_k<130><<<GG, 256>>>(xc2, W3, dinv + 2 * NN, u3);
    gemm_k<129><<<GG, 256>>>(xfd, W2, dinv + 3 * NN, u4);

    // 5) layer chain: gather + fused epilogue
    gather_epi_k<false, false><<<GW, 256>>>(csr, off, cnt, u1, dinv, b1,
                                            nullptr, nullptr, hp, 0 * NN);
    gather_epi_k<true,  false><<<GW, 256>>>(csr, off, cnt, u2, dinv, b2,
                                            hp, nullptr, hc1, 1 * NN);
    gather_epi_k<true,  false><<<GW, 256>>>(csr, off, cnt, u3, dinv, b3,
                                            hc1, nullptr, hc2, 2 * NN);
    gather_epi_k<true,  true ><<<GW, 256>>>(csr, off, cnt, u4, dinv, b2,
                                            hc2, hc1, hf, 3 * NN);

    // 6) final conv on relu(hf) with We, then fused gather + log_softmax
    gemm5_k<<<GN, 256>>>(hf, We, dinv + 3 * NN, u5);
    gather_final_k<<<GW, 256>>>(csr, off, cnt, u5, dinv, be, out, 3 * NN);
}

// round 16
// speedup vs baseline: 1.1918x; 1.1918x over previous
#include <cuda_runtime.h>

#define NN 100000
#define EE 3200000

// ---------------------------------------------------------------------------
// Scratch (float units): cnt[4N int] @0, dinv[4N] @400000, u1..u5, agg1..agg5,
// hp/hc1/hc2/hf. 22.4M floats ~ 90 MB.
// ---------------------------------------------------------------------------
__device__ float g_scratch[22400000];

static const long O_CNT  = 0;
static const long O_DINV = 400000;
static const long O_U1   = 800000;
static const long O_U2   = 2400000;
static const long O_U3   = 4000000;
static const long O_U4   = 5600000;
static const long O_U5   = 7200000;   // stride 12
static const long O_A1   = 8400000;
static const long O_A2   = 10000000;
static const long O_A3   = 11600000;
static const long O_A4   = 13200000;
static const long O_A5   = 14800000;  // stride 12
static const long O_HP   = 16000000;
static const long O_HC1  = 17600000;
static const long O_HC2  = 19200000;
static const long O_HF   = 20800000;

// ---------------------------------------------------------------------------
// Zero: cnt (100000 float4) + agg region (1,900,000 float4 @ idx 2,100,000)
// ---------------------------------------------------------------------------
__global__ void zero_k(float* __restrict__ S) {
    int i = blockIdx.x * 256 + threadIdx.x;
    if (i >= 2000000) return;
    long w = (i < 100000) ? (long)i : (long)(i - 100000) + 2100000;
    ((float4*)S)[w] = make_float4(0.f, 0.f, 0.f, 0.f);
}

// ---------------------------------------------------------------------------
// Fused degree histogram over dst for all 4 graphs.
// ---------------------------------------------------------------------------
__global__ void count4_k(const int* __restrict__ d0, const int* __restrict__ d1,
                         const int* __restrict__ d2, const int* __restrict__ d3,
                         int* __restrict__ cnt) {
    long t = (long)blockIdx.x * 256 + threadIdx.x;
    if (t >= 4L * EE) return;
    int g = (int)(t / EE);
    int e = (int)(t - (long)g * EE);
    const int* d = (g == 0) ? d0 : (g == 1) ? d1 : (g == 2) ? d2 : d3;
    atomicAdd(&cnt[g * NN + __ldg(d + e)], 1);
}

__global__ void dinv_k(const int* __restrict__ cnt, float* __restrict__ dinv) {
    int i = blockIdx.x * 256 + threadIdx.x;
    if (i < 4 * NN) dinv[i] = rsqrtf((float)cnt[i] + 1.0f);
}

// ---------------------------------------------------------------------------
// GEMM (quad-split): 256 threads, 64 nodes/block, 4 threads per node each
// computing 4 of the 16 outputs over the full K range.
// U[n][f] = dinv[n] * sum_k X[n][k] * W[k][f]
// ---------------------------------------------------------------------------
template<int F>
__global__ __launch_bounds__(256) void gemm_k(const float* __restrict__ X,
                                              const float* __restrict__ W,
                                              const float* __restrict__ dinv,
                                              float* __restrict__ U) {
    constexpr int FP = 132;
    __shared__ float xs[64 * FP];   // 33792 B
    __shared__ float ws[FP * 16];   //  8448 B
    const int tid = threadIdx.x;
    const int node0 = blockIdx.x * 64;

    for (int i = tid; i < FP * 16; i += 256)
        ws[i] = (i < F * 16) ? W[i] : 0.f;

    int valid = NN - node0; if (valid > 64) valid = 64;
    const int lim = valid * F;
    for (int i = tid; i < lim; i += 256) {
        int r = i / F;
        int k = i - r * F;
        xs[r * FP + k] = X[(long)node0 * F + i];
    }
    constexpr int PAD = FP - F;
    for (int i = tid; i < 64 * PAD; i += 256) {
        int r = i / PAD;
        int c = i - r * PAD;
        xs[r * FP + F + c] = 0.f;
    }
    __syncthreads();

    const int nl = tid >> 2;
    const int q  = tid & 3;
    const int n  = node0 + nl;
    if (n >= NN) return;

    float4 acc = make_float4(0.f, 0.f, 0.f, 0.f);
    const float* xr = xs + nl * FP;
    const float* wq = ws + q * 4;

#pragma unroll
    for (int k = 0; k < FP; k += 4) {
        float4 xv = *(const float4*)(xr + k);
        float4 w0 = *(const float4*)(wq + (k + 0) * 16);
        float4 w1 = *(const float4*)(wq + (k + 1) * 16);
        float4 w2 = *(const float4*)(wq + (k + 2) * 16);
        float4 w3 = *(const float4*)(wq + (k + 3) * 16);
        acc.x = fmaf(xv.x, w0.x, acc.x); acc.y = fmaf(xv.x, w0.y, acc.y);
        acc.z = fmaf(xv.x, w0.z, acc.z); acc.w = fmaf(xv.x, w0.w, acc.w);
        acc.x = fmaf(xv.y, w1.x, acc.x); acc.y = fmaf(xv.y, w1.y, acc.y);
        acc.z = fmaf(xv.y, w1.z, acc.z); acc.w = fmaf(xv.y, w1.w, acc.w);
        acc.x = fmaf(xv.z, w2.x, acc.x); acc.y = fmaf(xv.z, w2.y, acc.y);
        acc.z = fmaf(xv.z, w2.z, acc.z); acc.w = fmaf(xv.z, w2.w, acc.w);
        acc.x = fmaf(xv.w, w3.x, acc.x); acc.y = fmaf(xv.w, w3.y, acc.y);
        acc.z = fmaf(xv.w, w3.z, acc.z); acc.w = fmaf(xv.w, w3.w, acc.w);
    }

    const float dv = dinv[n];
    float4 r = make_float4(dv * acc.x, dv * acc.y, dv * acc.z, dv * acc.w);
    *(float4*)(U + (long)n * 16 + q * 4) = r;
}

// ---------------------------------------------------------------------------
// Edge scatter: agg[dst] += u[src]  (rows of ST floats; NQ float4 quarters).
// 4 lanes per edge; leader lane loads src/dst once, shfl-broadcast.
// float4 vector atomics (sm_90+): 1 RED.128 per quarter-row.
// ---------------------------------------------------------------------------
template<int ST, int NQ>
__global__ void scatter_k(const int* __restrict__ src, const int* __restrict__ dst,
                          const float* __restrict__ u, float* __restrict__ agg) {
    int t = blockIdx.x * 256 + threadIdx.x;
    int e = t >> 2;
    int q = t & 3;
    if (e >= EE) return;
    int s = 0, d = 0;
    if (q == 0) { s = __ldg(src + e); d = __ldg(dst + e); }
    int leader = (threadIdx.x & 31) & ~3;
    s = __shfl_sync(0xFFFFFFFFu, s, leader);
    d = __shfl_sync(0xFFFFFFFFu, d, leader);
    if (q >= NQ) return;
    float4 v = *(const float4*)(u + (long)s * ST + q * 4);
    atomicAdd((float4*)(agg + (long)d * ST + q * 4), v);
}

// ---------------------------------------------------------------------------
// Per-node epilogue: h = dinv*(agg + u) + b [+ relu(rA) + rA] [+ rB]
// ---------------------------------------------------------------------------
template<bool HAS_RA, bool HAS_RB>
__global__ void epi_k(const float* __restrict__ agg, const float* __restrict__ u,
                      const float* __restrict__ dinv, const float* __restrict__ b,
                      const float* __restrict__ rA, const float* __restrict__ rB,
                      float* __restrict__ h) {
    int n = blockIdx.x * 256 + threadIdx.x;
    if (n >= NN) return;
    float dv = dinv[n];
    const float4* A = (const float4*)agg + (long)n * 4;
    const float4* U = (const float4*)u   + (long)n * 4;
    const float4* B = (const float4*)b;
    float4* H = (float4*)h + (long)n * 4;
#pragma unroll
    for (int g = 0; g < 4; g++) {
        float4 a = A[g], uu = U[g], bb = B[g];
        float4 r;
        r.x = dv * (a.x + uu.x) + bb.x;
        r.y = dv * (a.y + uu.y) + bb.y;
        r.z = dv * (a.z + uu.z) + bb.z;
        r.w = dv * (a.w + uu.w) + bb.w;
        if (HAS_RA) {
            float4 t = ((const float4*)rA)[(long)n * 4 + g];
            r.x += fmaxf(t.x, 0.f) + t.x;
            r.y += fmaxf(t.y, 0.f) + t.y;
            r.z += fmaxf(t.z, 0.f) + t.z;
            r.w += fmaxf(t.w, 0.f) + t.w;
        }
        if (HAS_RB) {
            float4 t = ((const float4*)rB)[(long)n * 4 + g];
            r.x += t.x; r.y += t.y; r.z += t.z; r.w += t.w;
        }
        H[g] = r;
    }
}

// ---------------------------------------------------------------------------
// Layer-5 GEMM: u5[n] = dinv_fd[n] * (relu(hf[n]) @ We), rows padded to 12
// ---------------------------------------------------------------------------
__global__ void gemm5_k(const float* __restrict__ hf, const float* __restrict__ We,
                        const float* __restrict__ dinv_fd, float* __restrict__ u5) {
    __shared__ float ws[160];
    if (threadIdx.x < 160) ws[threadIdx.x] = We[threadIdx.x];
    __syncthreads();
    int n = blockIdx.x * 256 + threadIdx.x;
    if (n >= NN) return;
    float xf[16];
    const float4* H = (const float4*)hf + (long)n * 4;
#pragma unroll
    for (int g = 0; g < 4; g++) {
        float4 v = H[g];
        xf[4 * g + 0] = fmaxf(v.x, 0.f);
        xf[4 * g + 1] = fmaxf(v.y, 0.f);
        xf[4 * g + 2] = fmaxf(v.z, 0.f);
        xf[4 * g + 3] = fmaxf(v.w, 0.f);
    }
    float acc[10];
#pragma unroll
    for (int f = 0; f < 10; f++) acc[f] = 0.f;
#pragma unroll
    for (int k = 0; k < 16; k++) {
        float xk = xf[k];
#pragma unroll
        for (int f = 0; f < 10; f++) acc[f] = fmaf(xk, ws[k * 10 + f], acc[f]);
    }
    float dv = dinv_fd[n];
    long base = (long)n * 12;
#pragma unroll
    for (int f = 0; f < 10; f++) u5[base + f] = dv * acc[f];
    u5[base + 10] = 0.f;
    u5[base + 11] = 0.f;
}

// ---------------------------------------------------------------------------
// Final: o = dinv*(agg5 + u5) + be ; out = log_softmax(o) over 10 classes
// ---------------------------------------------------------------------------
__global__ void softmax_k(const float* __restrict__ agg5, const float* __restrict__ u5,
                          const float* __restrict__ dinv, const float* __restrict__ be,
                          float* __restrict__ out) {
    int n = blockIdx.x * 256 + threadIdx.x;
    if (n >= NN) return;
    float dv = dinv[n];
    long base = (long)n * 12;
    const float4* A = (const float4*)(agg5 + base);
    const float4* U = (const float4*)(u5 + base);
    float o[12];
#pragma unroll
    for (int g = 0; g < 3; g++) {
        float4 a = A[g], u = U[g];
        o[4 * g + 0] = dv * (a.x + u.x);
        o[4 * g + 1] = dv * (a.y + u.y);
        o[4 * g + 2] = dv * (a.z + u.z);
        o[4 * g + 3] = dv * (a.w + u.w);
    }
#pragma unroll
    for (int f = 0; f < 10; f++) o[f] += __ldg(be + f);
    float m = o[0];
#pragma unroll
    for (int f = 1; f < 10; f++) m = fmaxf(m, o[f]);
    float s = 0.f;
#pragma unroll
    for (int f = 0; f < 10; f++) s += expf(o[f] - m);
    float l = m + logf(s);
    long ob = (long)n * 10;
#pragma unroll
    for (int f = 0; f < 10; f++) out[ob + f] = o[f] - l;
}

// ---------------------------------------------------------------------------
// Launch
// ---------------------------------------------------------------------------
extern "C" void kernel_launch(void* const* d_in, const int* in_sizes, int n_in,
                              void* d_out, int out_size) {
    const float* xp  = (const float*)d_in[0];
    const float* xc1 = (const float*)d_in[1];
    const float* xc2 = (const float*)d_in[2];
    const float* xfd = (const float*)d_in[3];
    const int*   ep  = (const int*)d_in[4];
    const int*   ec1 = (const int*)d_in[5];
    const int*   ec2 = (const int*)d_in[6];
    const int*   efd = (const int*)d_in[7];
    const float* W1 = (const float*)d_in[8];
    const float* b1 = (const float*)d_in[9];
    const float* W2 = (const float*)d_in[10];
    const float* b2 = (const float*)d_in[11];
    const float* W3 = (const float*)d_in[12];
    const float* b3 = (const float*)d_in[13];
    const float* We = (const float*)d_in[14];
    const float* be = (const float*)d_in[15];
    float* out = (float*)d_out;

    float* S = nullptr;
    cudaGetSymbolAddress((void**)&S, g_scratch);

    int*   cnt  = (int*)(S + O_CNT);
    float* dinv = S + O_DINV;   // [parent | c1 | c2 | fd], each N
    float* u1 = S + O_U1, *u2 = S + O_U2, *u3 = S + O_U3, *u4 = S + O_U4, *u5 = S + O_U5;
    float* a1 = S + O_A1, *a2 = S + O_A2, *a3 = S + O_A3, *a4 = S + O_A4, *a5 = S + O_A5;
    float* hp = S + O_HP, *hc1 = S + O_HC1, *hc2 = S + O_HC2, *hf = S + O_HF;

    const int GN = (NN + 255) / 256;                 // 391
    const int GG = (NN + 63) / 64;                   // 1563
    const int GC = (int)((4L * EE + 255) / 256);     // 50000
    const int GS = (EE * 4) / 256;                   // 50000
    const int GZ = (2000000 + 255) / 256;

    // 1) zero counters + all agg buffers
    zero_k<<<GZ, 256>>>(S);

    // 2) fused degree histograms (dst rows = second half of each [2,E])
    count4_k<<<GC, 256>>>(ep + EE, ec1 + EE, ec2 + EE, efd + EE, cnt);
    dinv_k<<<(4 * NN + 255) / 256, 256>>>(cnt, dinv);

    // 3) dense GEMMs with dinv pre-scaling (u = dinv .* (x @ W)) — quad-split
    gemm_k<128><<<GG, 256>>>(xp,  W1, dinv + 0 * NN, u1);
    gemm_k<129><<<GG, 256>>>(xc1, W2, dinv + 1 * NN, u2);
    gemm_k<130><<<GG, 256>>>(xc2, W3, dinv + 2 * NN, u3);
    gemm_k<129><<<GG, 256>>>(xfd, W2, dinv + 3 * NN, u4);

    // 4) layer chain: vector-atomic scatter + fused epilogue
    scatter_k<16, 4><<<GS, 256>>>(ep, ep + EE, u1, a1);
    epi_k<false, false><<<GN, 256>>>(a1, u1, dinv + 0 * NN, b1, nullptr, nullptr, hp);

    scatter_k<16, 4><<<GS, 256>>>(ec1, ec1 + EE, u2, a2);
    epi_k<true, false><<<GN, 256>>>(a2, u2, dinv + 1 * NN, b2, hp, nullptr, hc1);

    scatter_k<16, 4><<<GS, 256>>>(ec2, ec2 + EE, u3, a3);
    epi_k<true, false><<<GN, 256>>>(a3, u3, dinv + 2 * NN, b3, hc1, nullptr, hc2);

    scatter_k<16, 4><<<GS, 256>>>(efd, efd + EE, u4, a4);
    epi_k<true, true><<<GN, 256>>>(a4, u4, dinv + 3 * NN, b2, hc2, hc1, hf);

    // 5) final conv on relu(hf) with We, then log_softmax
    gemm5_k<<<GN, 256>>>(hf, We, dinv + 3 * NN, u5);
    scatter_k<12, 3><<<GS, 256>>>(efd, efd + EE, u5, a5);
    softmax_k<<<GN, 256>>>(a5, u5, dinv + 3 * NN, be, out);
}